// round 8
// baseline (speedup 1.0000x reference)
#include <cuda_runtime.h>
#include <cuda_bf16.h>
#include <cstdint>

// Problem constants (B=64, H=W=56, C=256, heads=8, hd=32, ws=7, shift=3)
#define IMG 56
#define CH 256
#define NHEAD 8
#define HD 32
#define WS 7
#define NWIN 64
#define NTOK 49
#define BATCH 64
#define M_TOTAL (BATCH * IMG * IMG)   // 200704
#define QKV_N 768
#define QSCALE 0.17677669529663687f

// Scratch
__device__ float g_qkv[(size_t)M_TOTAL * QKV_N];               // fp32 qkv (window order)
__device__ __nv_bfloat16 g_x_hi[(size_t)M_TOTAL * CH];
__device__ __nv_bfloat16 g_x_lo[(size_t)M_TOTAL * CH];
__device__ __nv_bfloat16 g_wq_hi[(size_t)QKV_N * CH];
__device__ __nv_bfloat16 g_wq_lo[(size_t)QKV_N * CH];
__device__ __nv_bfloat16 g_wp_hi[(size_t)CH * CH];
__device__ __nv_bfloat16 g_wp_lo[(size_t)CH * CH];
__device__ __nv_bfloat16 g_ao_hi[(size_t)M_TOTAL * CH];
__device__ __nv_bfloat16 g_ao_lo[(size_t)M_TOTAL * CH];

// ---- index helper ------------------------------------------------------
__device__ __forceinline__ int gather_src_row(int m) {
    int win = m / NTOK, n = m - win * NTOK;
    int b = win >> 6, wl = win & 63;
    int hr = (wl >> 3) * WS + n / WS;
    int wr = (wl & 7) * WS + n % WS;
    int h = hr + 3; if (h >= IMG) h -= IMG;
    int w = wr + 3; if (w >= IMG) w -= IMG;
    return (b * IMG + h) * IMG + w;
}

__device__ __forceinline__ void split_pack(float a, float b, uint32_t& hi, uint32_t& lo) {
    __nv_bfloat16 ha = __float2bfloat16_rn(a), hb = __float2bfloat16_rn(b);
    __nv_bfloat16 la = __float2bfloat16_rn(a - __bfloat162float(ha));
    __nv_bfloat16 lb = __float2bfloat16_rn(b - __bfloat162float(hb));
    __nv_bfloat162 h2; h2.x = ha; h2.y = hb;
    __nv_bfloat162 l2; l2.x = la; l2.y = lb;
    hi = *reinterpret_cast<uint32_t*>(&h2);
    lo = *reinterpret_cast<uint32_t*>(&l2);
}

__device__ __forceinline__ void mma16816(float* c,
    uint32_t a0, uint32_t a1, uint32_t a2, uint32_t a3,
    uint32_t b0, uint32_t b1) {
    asm volatile(
        "mma.sync.aligned.m16n8k16.row.col.f32.bf16.bf16.f32 "
        "{%0,%1,%2,%3}, {%4,%5,%6,%7}, {%8,%9}, {%0,%1,%2,%3};"
        : "+f"(c[0]), "+f"(c[1]), "+f"(c[2]), "+f"(c[3])
        : "r"(a0), "r"(a1), "r"(a2), "r"(a3), "r"(b0), "r"(b1));
}

__device__ __forceinline__ void cp_async16(uint32_t dst, const void* src) {
    asm volatile("cp.async.cg.shared.global [%0], [%1], 16;" :: "r"(dst), "l"(src));
}
__device__ __forceinline__ void cp_commit() {
    asm volatile("cp.async.commit_group;");
}
__device__ __forceinline__ void cp_wait0() {
    asm volatile("cp.async.wait_group 0;");
}

// ---- prep kernels ------------------------------------------------------
__global__ void __launch_bounds__(256) prep_x(const float* __restrict__ x) {
    int idx = blockIdx.x * 256 + threadIdx.x;
    int m = idx >> 6;
    int k4 = (idx & 63) * 4;
    float4 v = *(const float4*)(x + (size_t)gather_src_row(m) * CH + k4);
    uint32_t h0, l0, h1, l1;
    split_pack(v.x, v.y, h0, l0);
    split_pack(v.z, v.w, h1, l1);
    *(uint2*)(g_x_hi + (size_t)m * CH + k4) = make_uint2(h0, h1);
    *(uint2*)(g_x_lo + (size_t)m * CH + k4) = make_uint2(l0, l1);
}

__global__ void __launch_bounds__(256) prep_w(const float* __restrict__ w,
                                              __nv_bfloat16* __restrict__ whi,
                                              __nv_bfloat16* __restrict__ wlo) {
    int idx = blockIdx.x * 256 + threadIdx.x;
    float4 v = *(const float4*)(w + (size_t)idx * 4);
    uint32_t h0, l0, h1, l1;
    split_pack(v.x, v.y, h0, l0);
    split_pack(v.z, v.w, h1, l1);
    *(uint2*)(whi + (size_t)idx * 4) = make_uint2(h0, h1);
    *(uint2*)(wlo + (size_t)idx * 4) = make_uint2(l0, l1);
}

// ---- HMMA GEMM: 128x256 tile, 512 threads, BK=32, cp.async double buffer
#define BK 32
#define SA 40
#define A_ELEMS (128 * SA)
#define B_ELEMS (256 * SA)
#define A_BYTES (A_ELEMS * 2)
#define B_BYTES (B_ELEMS * 2)
#define STG_ELEMS (2 * A_ELEMS + 2 * B_ELEMS)
#define STG_BYTES (STG_ELEMS * 2)
#define SMEM_GEMM (2 * STG_BYTES)

template <int MODE>
__global__ void __launch_bounds__(512, 1) tc_gemm(
    const __nv_bfloat16* __restrict__ Ahi_g, const __nv_bfloat16* __restrict__ Alo_g,
    const __nv_bfloat16* __restrict__ Whi_g, const __nv_bfloat16* __restrict__ Wlo_g,
    const float* __restrict__ bias, float* __restrict__ out)
{
    extern __shared__ __nv_bfloat16 sm[];
    const int tid = threadIdx.x;
    const int wid = tid >> 5;
    const int lane = tid & 31;
    const int gid = lane >> 2;
    const int t4 = lane & 3;
    const int wm = wid & 3;
    const int wn = wid >> 2;
    const int bm = blockIdx.y * 128;
    const int bn = blockIdx.x * 256;
    const int OUT_STRIDE = (MODE == 0) ? QKV_N : CH;

    const uint32_t smem_base = (uint32_t)__cvta_generic_to_shared(sm);

    const int arow = tid >> 2;
    const int ak = (tid & 3) * 8;
    const int brow = tid >> 1;
    const int bk = (tid & 1) * 16;
    const __nv_bfloat16* Ah_g = Ahi_g + (size_t)(bm + arow) * CH + ak;
    const __nv_bfloat16* Al_g = Alo_g + (size_t)(bm + arow) * CH + ak;
    const __nv_bfloat16* Bh_g = Whi_g + (size_t)(bn + brow) * CH + bk;
    const __nv_bfloat16* Bl_g = Wlo_g + (size_t)(bn + brow) * CH + bk;

    const uint32_t sA = (uint32_t)((arow * SA + ak) * 2);
    const uint32_t sB = (uint32_t)(2 * A_BYTES + (brow * SA + bk) * 2);

    auto load_stage = [&](int st, int k0) {
        const uint32_t base = smem_base + st * STG_BYTES;
        cp_async16(base + sA, Ah_g + k0);
        cp_async16(base + sA + A_BYTES, Al_g + k0);
        cp_async16(base + sB, Bh_g + k0);
        cp_async16(base + sB + 16, Bh_g + k0 + 8);
        cp_async16(base + sB + B_BYTES, Bl_g + k0);
        cp_async16(base + sB + B_BYTES + 16, Bl_g + k0 + 8);
        cp_commit();
    };

    float acc[2][8][4];
#pragma unroll
    for (int mt = 0; mt < 2; mt++)
#pragma unroll
        for (int nt = 0; nt < 8; nt++)
#pragma unroll
            for (int r = 0; r < 4; r++) acc[mt][nt][r] = 0.f;

    load_stage(0, 0);
    cp_wait0();
    __syncthreads();

    const int NSTAGE = CH / BK;   // 8
    for (int s = 0; s < NSTAGE; s++) {
        const int p = s & 1;
        if (s + 1 < NSTAGE) load_stage((s + 1) & 1, (s + 1) * BK);

        const __nv_bfloat16* Ah = sm + p * STG_ELEMS;
        const __nv_bfloat16* Al = Ah + A_ELEMS;
        const __nv_bfloat16* Bh = Ah + 2 * A_ELEMS;
        const __nv_bfloat16* Bl = Bh + B_ELEMS;
#pragma unroll
        for (int ksub = 0; ksub < 2; ksub++) {
            const int kk = ksub * 16 + 2 * t4;
            uint32_t ah[2][4], al[2][4];
#pragma unroll
            for (int mt = 0; mt < 2; mt++) {
                int r = wm * 32 + mt * 16 + gid;
                ah[mt][0] = *(const uint32_t*)(Ah + r * SA + kk);
                ah[mt][1] = *(const uint32_t*)(Ah + (r + 8) * SA + kk);
                ah[mt][2] = *(const uint32_t*)(Ah + r * SA + kk + 8);
                ah[mt][3] = *(const uint32_t*)(Ah + (r + 8) * SA + kk + 8);
                al[mt][0] = *(const uint32_t*)(Al + r * SA + kk);
                al[mt][1] = *(const uint32_t*)(Al + (r + 8) * SA + kk);
                al[mt][2] = *(const uint32_t*)(Al + r * SA + kk + 8);
                al[mt][3] = *(const uint32_t*)(Al + (r + 8) * SA + kk + 8);
            }
            // pass 1: ah * Bh  (each acc touched once per pass -> reuse distance 16)
#pragma unroll
            for (int nt = 0; nt < 8; nt++) {
                int c = wn * 64 + nt * 8 + gid;
                uint32_t b0 = *(const uint32_t*)(Bh + c * SA + kk);
                uint32_t b1 = *(const uint32_t*)(Bh + c * SA + kk + 8);
                mma16816(acc[0][nt], ah[0][0], ah[0][1], ah[0][2], ah[0][3], b0, b1);
                mma16816(acc[1][nt], ah[1][0], ah[1][1], ah[1][2], ah[1][3], b0, b1);
            }
            // pass 2: ah * Bl
#pragma unroll
            for (int nt = 0; nt < 8; nt++) {
                int c = wn * 64 + nt * 8 + gid;
                uint32_t b0 = *(const uint32_t*)(Bl + c * SA + kk);
                uint32_t b1 = *(const uint32_t*)(Bl + c * SA + kk + 8);
                mma16816(acc[0][nt], ah[0][0], ah[0][1], ah[0][2], ah[0][3], b0, b1);
                mma16816(acc[1][nt], ah[1][0], ah[1][1], ah[1][2], ah[1][3], b0, b1);
            }
            // pass 3: al * Bh
#pragma unroll
            for (int nt = 0; nt < 8; nt++) {
                int c = wn * 64 + nt * 8 + gid;
                uint32_t b0 = *(const uint32_t*)(Bh + c * SA + kk);
                uint32_t b1 = *(const uint32_t*)(Bh + c * SA + kk + 8);
                mma16816(acc[0][nt], al[0][0], al[0][1], al[0][2], al[0][3], b0, b1);
                mma16816(acc[1][nt], al[1][0], al[1][1], al[1][2], al[1][3], b0, b1);
            }
        }
        if (s + 1 < NSTAGE) {
            cp_wait0();
            __syncthreads();
        }
    }

#pragma unroll
    for (int mt = 0; mt < 2; mt++) {
        int m1 = bm + wm * 32 + mt * 16 + gid;
        int m2 = m1 + 8;
        float* d1;
        float* d2;
        if (MODE == 0) {
            d1 = out + (size_t)m1 * OUT_STRIDE;
            d2 = out + (size_t)m2 * OUT_STRIDE;
        } else {
            d1 = out + (size_t)gather_src_row(m1) * OUT_STRIDE;
            d2 = out + (size_t)gather_src_row(m2) * OUT_STRIDE;
        }
#pragma unroll
        for (int nt = 0; nt < 8; nt++) {
            int n = bn + wn * 64 + nt * 8 + 2 * t4;
            float2 bv2 = *(const float2*)(bias + n);
            float2 r1, r2;
            r1.x = acc[mt][nt][0] + bv2.x; r1.y = acc[mt][nt][1] + bv2.y;
            r2.x = acc[mt][nt][2] + bv2.x; r2.y = acc[mt][nt][3] + bv2.y;
            *(float2*)(d1 + n) = r1;
            *(float2*)(d2 + n) = r2;
        }
    }
}

// ---- HMMA window attention: one warp per (window, head) -----------------
__global__ void __launch_bounds__(32) attn_mma_kernel(
    const float* __restrict__ qkv, const float* __restrict__ table)
{
    const int blk = blockIdx.x;
    const int win = blk >> 3;
    const int head = blk & 7;
    const int lane = threadIdx.x;
    const int gid = lane >> 2;
    const int t4 = lane & 3;
    const int wl = win & 63;
    const int hbase = (wl >> 3) * WS;
    const int wbase = (wl & 7) * WS;

    __shared__ uint32_t KH[64 * 17], KL[64 * 17];
    __shared__ uint32_t VTH[32 * 33], VTL[32 * 33];
    __shared__ float TBL[169];

    for (int t = lane; t < 169; t += 32) TBL[t] = table[t * NHEAD + head];

    const float* base = qkv + (size_t)win * NTOK * QKV_N + head * HD;

    for (int r = lane; r < 64; r += 32) {
        bool valid = r < NTOK;
        const float* p = base + (size_t)(valid ? r : 0) * QKV_N + 256;
#pragma unroll
        for (int j = 0; j < 8; j++) {
            float4 kv = valid ? *(const float4*)(p + 4 * j) : make_float4(0, 0, 0, 0);
            uint32_t h0, l0, h1, l1;
            split_pack(kv.x, kv.y, h0, l0); split_pack(kv.z, kv.w, h1, l1);
            KH[r * 17 + 2 * j] = h0; KH[r * 17 + 2 * j + 1] = h1;
            KL[r * 17 + 2 * j] = l0; KL[r * 17 + 2 * j + 1] = l1;
        }
    }

    const float* vbase = base + 512;
#pragma unroll 4
    for (int tp = 0; tp < 32; tp++) {
        int t0 = 2 * tp, t1 = 2 * tp + 1;
        float a = (t0 < NTOK) ? vbase[(size_t)t0 * QKV_N + lane] : 0.f;
        float b = (t1 < NTOK) ? vbase[(size_t)t1 * QKV_N + lane] : 0.f;
        uint32_t h, l; split_pack(a, b, h, l);
        VTH[lane * 33 + tp] = h; VTL[lane * 33 + tp] = l;
    }
    __syncwarp();

    float o[4][4][4];
#pragma unroll
    for (int a = 0; a < 4; a++)
#pragma unroll
        for (int b = 0; b < 4; b++)
#pragma unroll
            for (int r = 0; r < 4; r++) o[a][b][r] = 0.f;

#pragma unroll
    for (int mt = 0; mt < 4; mt++) {
        const int r0 = mt * 16 + gid;
        const int rc0 = min(r0, NTOK - 1);
        const int rc1 = min(r0 + 8, NTOK - 1);
        const float* q0 = base + (size_t)rc0 * QKV_N;
        const float* q1 = base + (size_t)rc1 * QKV_N;

        uint32_t qh[2][4], ql[2][4];
#pragma unroll
        for (int ks = 0; ks < 2; ks++) {
            const int f0 = ks * 16 + 2 * t4;
            float2 x00 = *(const float2*)(q0 + f0);
            float2 x10 = *(const float2*)(q1 + f0);
            float2 x01 = *(const float2*)(q0 + f0 + 8);
            float2 x11 = *(const float2*)(q1 + f0 + 8);
            x00.x *= QSCALE; x00.y *= QSCALE; x10.x *= QSCALE; x10.y *= QSCALE;
            x01.x *= QSCALE; x01.y *= QSCALE; x11.x *= QSCALE; x11.y *= QSCALE;
            split_pack(x00.x, x00.y, qh[ks][0], ql[ks][0]);
            split_pack(x10.x, x10.y, qh[ks][1], ql[ks][1]);
            split_pack(x01.x, x01.y, qh[ks][2], ql[ks][2]);
            split_pack(x11.x, x11.y, qh[ks][3], ql[ks][3]);
        }

        float c[8][4];
#pragma unroll
        for (int nt = 0; nt < 8; nt++) { c[nt][0] = c[nt][1] = c[nt][2] = c[nt][3] = 0.f; }

        // QK passes: product-type outer, ks then nt inner (reuse distance 8)
#pragma unroll
        for (int ks = 0; ks < 2; ks++) {
            const int cp = ks * 8 + t4;
#pragma unroll
            for (int nt = 0; nt < 8; nt++) {
                int cn = nt * 8 + gid;
                uint32_t b0 = KH[cn * 17 + cp], b1 = KH[cn * 17 + cp + 4];
                mma16816(c[nt], qh[ks][0], qh[ks][1], qh[ks][2], qh[ks][3], b0, b1);
            }
        }
#pragma unroll
        for (int ks = 0; ks < 2; ks++) {
            const int cp = ks * 8 + t4;
#pragma unroll
            for (int nt = 0; nt < 8; nt++) {
                int cn = nt * 8 + gid;
                uint32_t b0 = KL[cn * 17 + cp], b1 = KL[cn * 17 + cp + 4];
                mma16816(c[nt], qh[ks][0], qh[ks][1], qh[ks][2], qh[ks][3], b0, b1);
            }
        }
#pragma unroll
        for (int ks = 0; ks < 2; ks++) {
            const int cp = ks * 8 + t4;
#pragma unroll
            for (int nt = 0; nt < 8; nt++) {
                int cn = nt * 8 + gid;
                uint32_t b0 = KH[cn * 17 + cp], b1 = KH[cn * 17 + cp + 4];
                mma16816(c[nt], ql[ks][0], ql[ks][1], ql[ks][2], ql[ks][3], b0, b1);
            }
        }

        // bias + shift mask + padding mask
        const int ih0 = rc0 / WS, iw0 = rc0 % WS;
        const int ih1 = rc1 / WS, iw1 = rc1 % WS;
        int hr, wr, rh, rw;
        hr = hbase + ih0; wr = wbase + iw0;
        rh = (hr < 49) ? 0 : ((hr < 53) ? 1 : 2); rw = (wr < 49) ? 0 : ((wr < 53) ? 1 : 2);
        const int rg0 = rh * 3 + rw;
        hr = hbase + ih1; wr = wbase + iw1;
        rh = (hr < 49) ? 0 : ((hr < 53) ? 1 : 2); rw = (wr < 49) ? 0 : ((wr < 53) ? 1 : 2);
        const int rg1 = rh * 3 + rw;

#pragma unroll
        for (int nt = 0; nt < 8; nt++) {
#pragma unroll
            for (int jc = 0; jc < 2; jc++) {
                int j = nt * 8 + 2 * t4 + jc;
                if (j < NTOK) {
                    int jh = j / WS, jw = j % WS;
                    int jhr = hbase + jh, jwr = wbase + jw;
                    int rjh = (jhr < 49) ? 0 : ((jhr < 53) ? 1 : 2);
                    int rjw = (jwr < 49) ? 0 : ((jwr < 53) ? 1 : 2);
                    int rgj = rjh * 3 + rjw;
                    float b0 = TBL[(ih0 - jh + 6) * 13 + (iw0 - jw + 6)];
                    float b1 = TBL[(ih1 - jh + 6) * 13 + (iw1 - jw + 6)];
                    if (rg0 != rgj) b0 -= 100.f;
                    if (rg1 != rgj) b1 -= 100.f;
                    c[nt][jc] += b0;
                    c[nt][2 + jc] += b1;
                } else {
                    c[nt][jc] = -1e30f;
                    c[nt][2 + jc] = -1e30f;
                }
            }
        }

        // softmax over t4 quad
        float m0 = -1e30f, m1 = -1e30f;
#pragma unroll
        for (int nt = 0; nt < 8; nt++) {
            m0 = fmaxf(m0, fmaxf(c[nt][0], c[nt][1]));
            m1 = fmaxf(m1, fmaxf(c[nt][2], c[nt][3]));
        }
        m0 = fmaxf(m0, __shfl_xor_sync(0xffffffffu, m0, 1));
        m0 = fmaxf(m0, __shfl_xor_sync(0xffffffffu, m0, 2));
        m1 = fmaxf(m1, __shfl_xor_sync(0xffffffffu, m1, 1));
        m1 = fmaxf(m1, __shfl_xor_sync(0xffffffffu, m1, 2));
        float s0 = 0.f, s1 = 0.f;
#pragma unroll
        for (int nt = 0; nt < 8; nt++) {
            c[nt][0] = __expf(c[nt][0] - m0); s0 += c[nt][0];
            c[nt][1] = __expf(c[nt][1] - m0); s0 += c[nt][1];
            c[nt][2] = __expf(c[nt][2] - m1); s1 += c[nt][2];
            c[nt][3] = __expf(c[nt][3] - m1); s1 += c[nt][3];
        }
        s0 += __shfl_xor_sync(0xffffffffu, s0, 1);
        s0 += __shfl_xor_sync(0xffffffffu, s0, 2);
        s1 += __shfl_xor_sync(0xffffffffu, s1, 1);
        s1 += __shfl_xor_sync(0xffffffffu, s1, 2);
        const float inv0 = 1.f / s0, inv1 = 1.f / s1;
#pragma unroll
        for (int nt = 0; nt < 8; nt++) {
            c[nt][0] *= inv0; c[nt][1] *= inv0;
            c[nt][2] *= inv1; c[nt][3] *= inv1;
        }

        // O += P V : per kt, product-type passes over nt (reuse distance 4)
#pragma unroll
        for (int kt = 0; kt < 4; kt++) {
            uint32_t ph[4], pl[4];
            split_pack(c[2 * kt][0],     c[2 * kt][1],     ph[0], pl[0]);
            split_pack(c[2 * kt][2],     c[2 * kt][3],     ph[1], pl[1]);
            split_pack(c[2 * kt + 1][0], c[2 * kt + 1][1], ph[2], pl[2]);
            split_pack(c[2 * kt + 1][2], c[2 * kt + 1][3], ph[3], pl[3]);
#pragma unroll
            for (int nt = 0; nt < 4; nt++) {
                int dn = nt * 8 + gid;
                uint32_t b0 = VTH[dn * 33 + kt * 8 + t4];
                uint32_t b1 = VTH[dn * 33 + kt * 8 + t4 + 4];
                mma16816(o[mt][nt], ph[0], ph[1], ph[2], ph[3], b0, b1);
            }
#pragma unroll
            for (int nt = 0; nt < 4; nt++) {
                int dn = nt * 8 + gid;
                uint32_t b0 = VTL[dn * 33 + kt * 8 + t4];
                uint32_t b1 = VTL[dn * 33 + kt * 8 + t4 + 4];
                mma16816(o[mt][nt], ph[0], ph[1], ph[2], ph[3], b0, b1);
            }
#pragma unroll
            for (int nt = 0; nt < 4; nt++) {
                int dn = nt * 8 + gid;
                uint32_t b0 = VTH[dn * 33 + kt * 8 + t4];
                uint32_t b1 = VTH[dn * 33 + kt * 8 + t4 + 4];
                mma16816(o[mt][nt], pl[0], pl[1], pl[2], pl[3], b0, b1);
            }
        }
    }

    // store O split into bf16 hi/lo scratch (input to proj GEMM)
#pragma unroll
    for (int mt = 0; mt < 4; mt++) {
        int i0 = mt * 16 + gid, i1 = i0 + 8;
#pragma unroll
        for (int nt = 0; nt < 4; nt++) {
            int d = nt * 8 + 2 * t4;
            if (i0 < NTOK) {
                size_t off = ((size_t)win * NTOK + i0) * CH + head * HD + d;
                uint32_t h, l; split_pack(o[mt][nt][0], o[mt][nt][1], h, l);
                *(uint32_t*)(g_ao_hi + off) = h;
                *(uint32_t*)(g_ao_lo + off) = l;
            }
            if (i1 < NTOK) {
                size_t off = ((size_t)win * NTOK + i1) * CH + head * HD + d;
                uint32_t h, l; split_pack(o[mt][nt][2], o[mt][nt][3], h, l);
                *(uint32_t*)(g_ao_hi + off) = h;
                *(uint32_t*)(g_ao_lo + off) = l;
            }
        }
    }
}

extern "C" void kernel_launch(void* const* d_in, const int* in_sizes, int n_in,
                              void* d_out, int out_size) {
    const float* x      = (const float*)d_in[0];
    const float* qkv_w  = (const float*)d_in[1];
    const float* qkv_b  = (const float*)d_in[2];
    const float* proj_w = (const float*)d_in[3];
    const float* proj_b = (const float*)d_in[4];
    const float* table  = (const float*)d_in[5];
    float* out = (float*)d_out;

    float* qkv_buf;
    __nv_bfloat16 *xhi, *xlo, *wqhi, *wqlo, *wphi, *wplo, *aohi, *aolo;
    cudaGetSymbolAddress((void**)&qkv_buf, g_qkv);
    cudaGetSymbolAddress((void**)&xhi, g_x_hi);
    cudaGetSymbolAddress((void**)&xlo, g_x_lo);
    cudaGetSymbolAddress((void**)&wqhi, g_wq_hi);
    cudaGetSymbolAddress((void**)&wqlo, g_wq_lo);
    cudaGetSymbolAddress((void**)&wphi, g_wp_hi);
    cudaGetSymbolAddress((void**)&wplo, g_wp_lo);
    cudaGetSymbolAddress((void**)&aohi, g_ao_hi);
    cudaGetSymbolAddress((void**)&aolo, g_ao_lo);

    cudaFuncSetAttribute(tc_gemm<0>, cudaFuncAttributeMaxDynamicSharedMemorySize, SMEM_GEMM);
    cudaFuncSetAttribute(tc_gemm<1>, cudaFuncAttributeMaxDynamicSharedMemorySize, SMEM_GEMM);

    prep_x<<<(M_TOTAL * (CH / 4)) / 256, 256>>>(x);
    prep_w<<<(QKV_N * CH / 4) / 256, 256>>>(qkv_w, wqhi, wqlo);
    prep_w<<<(CH * CH / 4) / 256, 256>>>(proj_w, wphi, wplo);

    dim3 g1(QKV_N / 256, M_TOTAL / 128);   // (3, 1568)
    tc_gemm<0><<<g1, 512, SMEM_GEMM>>>(xhi, xlo, wqhi, wqlo, qkv_b, qkv_buf);

    attn_mma_kernel<<<BATCH * NWIN * NHEAD, 32>>>(qkv_buf, table);

    dim3 g3(CH / 256, M_TOTAL / 128);      // (1, 1568)
    tc_gemm<1><<<g3, 512, SMEM_GEMM>>>(aohi, aolo, wphi, wplo, proj_b, out);
}

// round 9
// speedup vs baseline: 1.0467x; 1.0467x over previous
#include <cuda_runtime.h>
#include <cuda_bf16.h>
#include <cstdint>

// Problem constants (B=64, H=W=56, C=256, heads=8, hd=32, ws=7, shift=3)
#define IMG 56
#define CH 256
#define NHEAD 8
#define HD 32
#define WS 7
#define NWIN 64
#define NTOK 49
#define BATCH 64
#define M_TOTAL (BATCH * IMG * IMG)   // 200704
#define QKV_N 768
#define QSCALE 0.17677669529663687f

// Scratch
__device__ float g_qkv[(size_t)M_TOTAL * QKV_N];               // fp32 qkv (window order)
__device__ __nv_bfloat16 g_x_hi[(size_t)M_TOTAL * CH];
__device__ __nv_bfloat16 g_x_lo[(size_t)M_TOTAL * CH];
__device__ __nv_bfloat16 g_wq_hi[(size_t)QKV_N * CH];
__device__ __nv_bfloat16 g_wq_lo[(size_t)QKV_N * CH];
__device__ __nv_bfloat16 g_wp_hi[(size_t)CH * CH];
__device__ __nv_bfloat16 g_wp_lo[(size_t)CH * CH];
__device__ __nv_bfloat16 g_ao_hi[(size_t)M_TOTAL * CH];
__device__ __nv_bfloat16 g_ao_lo[(size_t)M_TOTAL * CH];

// ---- index helper ------------------------------------------------------
__device__ __forceinline__ int gather_src_row(int m) {
    int win = m / NTOK, n = m - win * NTOK;
    int b = win >> 6, wl = win & 63;
    int hr = (wl >> 3) * WS + n / WS;
    int wr = (wl & 7) * WS + n % WS;
    int h = hr + 3; if (h >= IMG) h -= IMG;
    int w = wr + 3; if (w >= IMG) w -= IMG;
    return (b * IMG + h) * IMG + w;
}

__device__ __forceinline__ void split_pack(float a, float b, uint32_t& hi, uint32_t& lo) {
    __nv_bfloat16 ha = __float2bfloat16_rn(a), hb = __float2bfloat16_rn(b);
    __nv_bfloat16 la = __float2bfloat16_rn(a - __bfloat162float(ha));
    __nv_bfloat16 lb = __float2bfloat16_rn(b - __bfloat162float(hb));
    __nv_bfloat162 h2; h2.x = ha; h2.y = hb;
    __nv_bfloat162 l2; l2.x = la; l2.y = lb;
    hi = *reinterpret_cast<uint32_t*>(&h2);
    lo = *reinterpret_cast<uint32_t*>(&l2);
}

__device__ __forceinline__ void mma16816(float* c,
    uint32_t a0, uint32_t a1, uint32_t a2, uint32_t a3,
    uint32_t b0, uint32_t b1) {
    asm volatile(
        "mma.sync.aligned.m16n8k16.row.col.f32.bf16.bf16.f32 "
        "{%0,%1,%2,%3}, {%4,%5,%6,%7}, {%8,%9}, {%0,%1,%2,%3};"
        : "+f"(c[0]), "+f"(c[1]), "+f"(c[2]), "+f"(c[3])
        : "r"(a0), "r"(a1), "r"(a2), "r"(a3), "r"(b0), "r"(b1));
}

__device__ __forceinline__ void cp_async16(uint32_t dst, const void* src) {
    asm volatile("cp.async.cg.shared.global [%0], [%1], 16;" :: "r"(dst), "l"(src));
}
__device__ __forceinline__ void cp_commit() {
    asm volatile("cp.async.commit_group;");
}
__device__ __forceinline__ void cp_wait0() {
    asm volatile("cp.async.wait_group 0;");
}

// ---- prep kernels ------------------------------------------------------
__global__ void __launch_bounds__(256) prep_x(const float* __restrict__ x) {
    int idx = blockIdx.x * 256 + threadIdx.x;
    int m = idx >> 6;
    int k4 = (idx & 63) * 4;
    float4 v = *(const float4*)(x + (size_t)gather_src_row(m) * CH + k4);
    uint32_t h0, l0, h1, l1;
    split_pack(v.x, v.y, h0, l0);
    split_pack(v.z, v.w, h1, l1);
    *(uint2*)(g_x_hi + (size_t)m * CH + k4) = make_uint2(h0, h1);
    *(uint2*)(g_x_lo + (size_t)m * CH + k4) = make_uint2(l0, l1);
}

__global__ void __launch_bounds__(256) prep_w(const float* __restrict__ w,
                                              __nv_bfloat16* __restrict__ whi,
                                              __nv_bfloat16* __restrict__ wlo) {
    int idx = blockIdx.x * 256 + threadIdx.x;
    float4 v = *(const float4*)(w + (size_t)idx * 4);
    uint32_t h0, l0, h1, l1;
    split_pack(v.x, v.y, h0, l0);
    split_pack(v.z, v.w, h1, l1);
    *(uint2*)(whi + (size_t)idx * 4) = make_uint2(h0, h1);
    *(uint2*)(wlo + (size_t)idx * 4) = make_uint2(l0, l1);
}

// ---- HMMA GEMM: 128x128 tile, 256 threads, 2 CTAs/SM, BK=32 ------------
#define BK 32
#define SA 40
#define T_ELEMS (128 * SA)                  // 5120 bf16 per matrix tile
#define T_BYTES (T_ELEMS * 2)               // 10240
#define STG_ELEMS (4 * T_ELEMS)             // Ahi|Alo|Bhi|Blo
#define STG_BYTES (STG_ELEMS * 2)           // 40960
#define SMEM_GEMM (2 * STG_BYTES)           // 81920 per CTA (2 CTAs = 160KB/SM)

template <int MODE>
__global__ void __launch_bounds__(256, 2) tc_gemm(
    const __nv_bfloat16* __restrict__ Ahi_g, const __nv_bfloat16* __restrict__ Alo_g,
    const __nv_bfloat16* __restrict__ Whi_g, const __nv_bfloat16* __restrict__ Wlo_g,
    const float* __restrict__ bias, float* __restrict__ out)
{
    extern __shared__ __nv_bfloat16 sm[];
    const int tid = threadIdx.x;
    const int wid = tid >> 5;
    const int lane = tid & 31;
    const int gid = lane >> 2;
    const int t4 = lane & 3;
    const int wm = wid & 3;          // 4 row groups of 32
    const int wn = wid >> 2;         // 2 col groups of 64
    const int bm = blockIdx.y * 128;
    const int bn = blockIdx.x * 128;
    const int OUT_STRIDE = (MODE == 0) ? QKV_N : CH;

    const uint32_t smem_base = (uint32_t)__cvta_generic_to_shared(sm);

    // loaders: row = tid>>1 (0..127), k half = (tid&1)*16 (32 bytes = 2 cp)
    const int lrow = tid >> 1;
    const int lk = (tid & 1) * 16;
    const __nv_bfloat16* Ah_g = Ahi_g + (size_t)(bm + lrow) * CH + lk;
    const __nv_bfloat16* Al_g = Alo_g + (size_t)(bm + lrow) * CH + lk;
    const __nv_bfloat16* Bh_g = Whi_g + (size_t)(bn + lrow) * CH + lk;
    const __nv_bfloat16* Bl_g = Wlo_g + (size_t)(bn + lrow) * CH + lk;

    const uint32_t sRow = (uint32_t)((lrow * SA + lk) * 2);

    auto load_stage = [&](int st, int k0) {
        const uint32_t base = smem_base + st * STG_BYTES + sRow;
        cp_async16(base, Ah_g + k0);
        cp_async16(base + 16, Ah_g + k0 + 8);
        cp_async16(base + T_BYTES, Al_g + k0);
        cp_async16(base + T_BYTES + 16, Al_g + k0 + 8);
        cp_async16(base + 2 * T_BYTES, Bh_g + k0);
        cp_async16(base + 2 * T_BYTES + 16, Bh_g + k0 + 8);
        cp_async16(base + 3 * T_BYTES, Bl_g + k0);
        cp_async16(base + 3 * T_BYTES + 16, Bl_g + k0 + 8);
        cp_commit();
    };

    float acc[2][8][4];
#pragma unroll
    for (int mt = 0; mt < 2; mt++)
#pragma unroll
        for (int nt = 0; nt < 8; nt++)
#pragma unroll
            for (int r = 0; r < 4; r++) acc[mt][nt][r] = 0.f;

    load_stage(0, 0);
    cp_wait0();
    __syncthreads();

    const int NSTAGE = CH / BK;   // 8
    for (int s = 0; s < NSTAGE; s++) {
        const int p = s & 1;
        if (s + 1 < NSTAGE) load_stage((s + 1) & 1, (s + 1) * BK);

        const __nv_bfloat16* Ah = sm + p * STG_ELEMS;
        const __nv_bfloat16* Al = Ah + T_ELEMS;
        const __nv_bfloat16* Bh = Ah + 2 * T_ELEMS;
        const __nv_bfloat16* Bl = Ah + 3 * T_ELEMS;
#pragma unroll
        for (int ksub = 0; ksub < 2; ksub++) {
            const int kk = ksub * 16 + 2 * t4;
            uint32_t ah[2][4], al[2][4];
#pragma unroll
            for (int mt = 0; mt < 2; mt++) {
                int r = wm * 32 + mt * 16 + gid;
                ah[mt][0] = *(const uint32_t*)(Ah + r * SA + kk);
                ah[mt][1] = *(const uint32_t*)(Ah + (r + 8) * SA + kk);
                ah[mt][2] = *(const uint32_t*)(Ah + r * SA + kk + 8);
                ah[mt][3] = *(const uint32_t*)(Ah + (r + 8) * SA + kk + 8);
                al[mt][0] = *(const uint32_t*)(Al + r * SA + kk);
                al[mt][1] = *(const uint32_t*)(Al + (r + 8) * SA + kk);
                al[mt][2] = *(const uint32_t*)(Al + r * SA + kk + 8);
                al[mt][3] = *(const uint32_t*)(Al + (r + 8) * SA + kk + 8);
            }
#pragma unroll
            for (int nt = 0; nt < 8; nt++) {
                int c = wn * 64 + nt * 8 + gid;
                uint32_t bh0 = *(const uint32_t*)(Bh + c * SA + kk);
                uint32_t bh1 = *(const uint32_t*)(Bh + c * SA + kk + 8);
                uint32_t bl0 = *(const uint32_t*)(Bl + c * SA + kk);
                uint32_t bl1 = *(const uint32_t*)(Bl + c * SA + kk + 8);
#pragma unroll
                for (int mt = 0; mt < 2; mt++) {
                    mma16816(acc[mt][nt], ah[mt][0], ah[mt][1], ah[mt][2], ah[mt][3], bh0, bh1);
                    mma16816(acc[mt][nt], ah[mt][0], ah[mt][1], ah[mt][2], ah[mt][3], bl0, bl1);
                    mma16816(acc[mt][nt], al[mt][0], al[mt][1], al[mt][2], al[mt][3], bh0, bh1);
                }
            }
        }
        if (s + 1 < NSTAGE) {
            cp_wait0();
            __syncthreads();
        }
    }

#pragma unroll
    for (int mt = 0; mt < 2; mt++) {
        int m1 = bm + wm * 32 + mt * 16 + gid;
        int m2 = m1 + 8;
        float* d1;
        float* d2;
        if (MODE == 0) {
            d1 = out + (size_t)m1 * OUT_STRIDE;
            d2 = out + (size_t)m2 * OUT_STRIDE;
        } else {
            d1 = out + (size_t)gather_src_row(m1) * OUT_STRIDE;
            d2 = out + (size_t)gather_src_row(m2) * OUT_STRIDE;
        }
#pragma unroll
        for (int nt = 0; nt < 8; nt++) {
            int n = bn + wn * 64 + nt * 8 + 2 * t4;
            float2 bv2 = *(const float2*)(bias + n);
            float2 r1, r2;
            r1.x = acc[mt][nt][0] + bv2.x; r1.y = acc[mt][nt][1] + bv2.y;
            r2.x = acc[mt][nt][2] + bv2.x; r2.y = acc[mt][nt][3] + bv2.y;
            *(float2*)(d1 + n) = r1;
            *(float2*)(d2 + n) = r2;
        }
    }
}

// ---- HMMA window attention: one warp per (window, head) -----------------
__global__ void __launch_bounds__(32) attn_mma_kernel(
    const float* __restrict__ qkv, const float* __restrict__ table)
{
    const int blk = blockIdx.x;
    const int win = blk >> 3;
    const int head = blk & 7;
    const int lane = threadIdx.x;
    const int gid = lane >> 2;
    const int t4 = lane & 3;
    const int wl = win & 63;
    const int hbase = (wl >> 3) * WS;
    const int wbase = (wl & 7) * WS;

    __shared__ uint32_t KH[64 * 17], KL[64 * 17];
    __shared__ uint32_t VTH[32 * 33], VTL[32 * 33];
    __shared__ float TBL[169];

    for (int t = lane; t < 169; t += 32) TBL[t] = table[t * NHEAD + head];

    const float* base = qkv + (size_t)win * NTOK * QKV_N + head * HD;

    for (int r = lane; r < 64; r += 32) {
        bool valid = r < NTOK;
        const float* p = base + (size_t)(valid ? r : 0) * QKV_N + 256;
#pragma unroll
        for (int j = 0; j < 8; j++) {
            float4 kv = valid ? *(const float4*)(p + 4 * j) : make_float4(0, 0, 0, 0);
            uint32_t h0, l0, h1, l1;
            split_pack(kv.x, kv.y, h0, l0); split_pack(kv.z, kv.w, h1, l1);
            KH[r * 17 + 2 * j] = h0; KH[r * 17 + 2 * j + 1] = h1;
            KL[r * 17 + 2 * j] = l0; KL[r * 17 + 2 * j + 1] = l1;
        }
    }

    const float* vbase = base + 512;
#pragma unroll 4
    for (int tp = 0; tp < 32; tp++) {
        int t0 = 2 * tp, t1 = 2 * tp + 1;
        float a = (t0 < NTOK) ? vbase[(size_t)t0 * QKV_N + lane] : 0.f;
        float b = (t1 < NTOK) ? vbase[(size_t)t1 * QKV_N + lane] : 0.f;
        uint32_t h, l; split_pack(a, b, h, l);
        VTH[lane * 33 + tp] = h; VTL[lane * 33 + tp] = l;
    }
    __syncwarp();

    float o[4][4][4];
#pragma unroll
    for (int a = 0; a < 4; a++)
#pragma unroll
        for (int b = 0; b < 4; b++)
#pragma unroll
            for (int r = 0; r < 4; r++) o[a][b][r] = 0.f;

#pragma unroll
    for (int mt = 0; mt < 4; mt++) {
        const int r0 = mt * 16 + gid;
        const int rc0 = min(r0, NTOK - 1);
        const int rc1 = min(r0 + 8, NTOK - 1);
        const float* q0 = base + (size_t)rc0 * QKV_N;
        const float* q1 = base + (size_t)rc1 * QKV_N;

        uint32_t qh[2][4], ql[2][4];
#pragma unroll
        for (int ks = 0; ks < 2; ks++) {
            const int f0 = ks * 16 + 2 * t4;
            float2 x00 = *(const float2*)(q0 + f0);
            float2 x10 = *(const float2*)(q1 + f0);
            float2 x01 = *(const float2*)(q0 + f0 + 8);
            float2 x11 = *(const float2*)(q1 + f0 + 8);
            x00.x *= QSCALE; x00.y *= QSCALE; x10.x *= QSCALE; x10.y *= QSCALE;
            x01.x *= QSCALE; x01.y *= QSCALE; x11.x *= QSCALE; x11.y *= QSCALE;
            split_pack(x00.x, x00.y, qh[ks][0], ql[ks][0]);
            split_pack(x10.x, x10.y, qh[ks][1], ql[ks][1]);
            split_pack(x01.x, x01.y, qh[ks][2], ql[ks][2]);
            split_pack(x11.x, x11.y, qh[ks][3], ql[ks][3]);
        }

        float c[8][4];
#pragma unroll
        for (int nt = 0; nt < 8; nt++) { c[nt][0] = c[nt][1] = c[nt][2] = c[nt][3] = 0.f; }
#pragma unroll
        for (int nt = 0; nt < 8; nt++) {
            int cn = nt * 8 + gid;
#pragma unroll
            for (int ks = 0; ks < 2; ks++) {
                int cp = ks * 8 + t4;
                uint32_t bh0 = KH[cn * 17 + cp], bh1 = KH[cn * 17 + cp + 4];
                uint32_t bl0 = KL[cn * 17 + cp], bl1 = KL[cn * 17 + cp + 4];
                mma16816(c[nt], qh[ks][0], qh[ks][1], qh[ks][2], qh[ks][3], bh0, bh1);
                mma16816(c[nt], qh[ks][0], qh[ks][1], qh[ks][2], qh[ks][3], bl0, bl1);
                mma16816(c[nt], ql[ks][0], ql[ks][1], ql[ks][2], ql[ks][3], bh0, bh1);
            }
        }

        // bias + shift mask + padding mask
        const int ih0 = rc0 / WS, iw0 = rc0 % WS;
        const int ih1 = rc1 / WS, iw1 = rc1 % WS;
        int hr, wr, rh, rw;
        hr = hbase + ih0; wr = wbase + iw0;
        rh = (hr < 49) ? 0 : ((hr < 53) ? 1 : 2); rw = (wr < 49) ? 0 : ((wr < 53) ? 1 : 2);
        const int rg0 = rh * 3 + rw;
        hr = hbase + ih1; wr = wbase + iw1;
        rh = (hr < 49) ? 0 : ((hr < 53) ? 1 : 2); rw = (wr < 49) ? 0 : ((wr < 53) ? 1 : 2);
        const int rg1 = rh * 3 + rw;

#pragma unroll
        for (int nt = 0; nt < 8; nt++) {
#pragma unroll
            for (int jc = 0; jc < 2; jc++) {
                int j = nt * 8 + 2 * t4 + jc;
                if (j < NTOK) {
                    int jh = j / WS, jw = j % WS;
                    int jhr = hbase + jh, jwr = wbase + jw;
                    int rjh = (jhr < 49) ? 0 : ((jhr < 53) ? 1 : 2);
                    int rjw = (jwr < 49) ? 0 : ((jwr < 53) ? 1 : 2);
                    int rgj = rjh * 3 + rjw;
                    float b0 = TBL[(ih0 - jh + 6) * 13 + (iw0 - jw + 6)];
                    float b1 = TBL[(ih1 - jh + 6) * 13 + (iw1 - jw + 6)];
                    if (rg0 != rgj) b0 -= 100.f;
                    if (rg1 != rgj) b1 -= 100.f;
                    c[nt][jc] += b0;
                    c[nt][2 + jc] += b1;
                } else {
                    c[nt][jc] = -1e30f;
                    c[nt][2 + jc] = -1e30f;
                }
            }
        }

        // softmax over t4 quad
        float m0 = -1e30f, m1 = -1e30f;
#pragma unroll
        for (int nt = 0; nt < 8; nt++) {
            m0 = fmaxf(m0, fmaxf(c[nt][0], c[nt][1]));
            m1 = fmaxf(m1, fmaxf(c[nt][2], c[nt][3]));
        }
        m0 = fmaxf(m0, __shfl_xor_sync(0xffffffffu, m0, 1));
        m0 = fmaxf(m0, __shfl_xor_sync(0xffffffffu, m0, 2));
        m1 = fmaxf(m1, __shfl_xor_sync(0xffffffffu, m1, 1));
        m1 = fmaxf(m1, __shfl_xor_sync(0xffffffffu, m1, 2));
        float s0 = 0.f, s1 = 0.f;
#pragma unroll
        for (int nt = 0; nt < 8; nt++) {
            c[nt][0] = __expf(c[nt][0] - m0); s0 += c[nt][0];
            c[nt][1] = __expf(c[nt][1] - m0); s0 += c[nt][1];
            c[nt][2] = __expf(c[nt][2] - m1); s1 += c[nt][2];
            c[nt][3] = __expf(c[nt][3] - m1); s1 += c[nt][3];
        }
        s0 += __shfl_xor_sync(0xffffffffu, s0, 1);
        s0 += __shfl_xor_sync(0xffffffffu, s0, 2);
        s1 += __shfl_xor_sync(0xffffffffu, s1, 1);
        s1 += __shfl_xor_sync(0xffffffffu, s1, 2);
        const float inv0 = 1.f / s0, inv1 = 1.f / s1;
#pragma unroll
        for (int nt = 0; nt < 8; nt++) {
            c[nt][0] *= inv0; c[nt][1] *= inv0;
            c[nt][2] *= inv1; c[nt][3] *= inv1;
        }

        // O += P V
#pragma unroll
        for (int kt = 0; kt < 4; kt++) {
            uint32_t ph[4], pl[4];
            split_pack(c[2 * kt][0],     c[2 * kt][1],     ph[0], pl[0]);
            split_pack(c[2 * kt][2],     c[2 * kt][3],     ph[1], pl[1]);
            split_pack(c[2 * kt + 1][0], c[2 * kt + 1][1], ph[2], pl[2]);
            split_pack(c[2 * kt + 1][2], c[2 * kt + 1][3], ph[3], pl[3]);
#pragma unroll
            for (int nt = 0; nt < 4; nt++) {
                int dn = nt * 8 + gid;
                uint32_t bh0 = VTH[dn * 33 + kt * 8 + t4];
                uint32_t bh1 = VTH[dn * 33 + kt * 8 + t4 + 4];
                uint32_t bl0 = VTL[dn * 33 + kt * 8 + t4];
                uint32_t bl1 = VTL[dn * 33 + kt * 8 + t4 + 4];
                mma16816(o[mt][nt], ph[0], ph[1], ph[2], ph[3], bh0, bh1);
                mma16816(o[mt][nt], ph[0], ph[1], ph[2], ph[3], bl0, bl1);
                mma16816(o[mt][nt], pl[0], pl[1], pl[2], pl[3], bh0, bh1);
            }
        }
    }

    // store O split into bf16 hi/lo scratch (input to proj GEMM)
#pragma unroll
    for (int mt = 0; mt < 4; mt++) {
        int i0 = mt * 16 + gid, i1 = i0 + 8;
#pragma unroll
        for (int nt = 0; nt < 4; nt++) {
            int d = nt * 8 + 2 * t4;
            if (i0 < NTOK) {
                size_t off = ((size_t)win * NTOK + i0) * CH + head * HD + d;
                uint32_t h, l; split_pack(o[mt][nt][0], o[mt][nt][1], h, l);
                *(uint32_t*)(g_ao_hi + off) = h;
                *(uint32_t*)(g_ao_lo + off) = l;
            }
            if (i1 < NTOK) {
                size_t off = ((size_t)win * NTOK + i1) * CH + head * HD + d;
                uint32_t h, l; split_pack(o[mt][nt][2], o[mt][nt][3], h, l);
                *(uint32_t*)(g_ao_hi + off) = h;
                *(uint32_t*)(g_ao_lo + off) = l;
            }
        }
    }
}

extern "C" void kernel_launch(void* const* d_in, const int* in_sizes, int n_in,
                              void* d_out, int out_size) {
    const float* x      = (const float*)d_in[0];
    const float* qkv_w  = (const float*)d_in[1];
    const float* qkv_b  = (const float*)d_in[2];
    const float* proj_w = (const float*)d_in[3];
    const float* proj_b = (const float*)d_in[4];
    const float* table  = (const float*)d_in[5];
    float* out = (float*)d_out;

    float* qkv_buf;
    __nv_bfloat16 *xhi, *xlo, *wqhi, *wqlo, *wphi, *wplo, *aohi, *aolo;
    cudaGetSymbolAddress((void**)&qkv_buf, g_qkv);
    cudaGetSymbolAddress((void**)&xhi, g_x_hi);
    cudaGetSymbolAddress((void**)&xlo, g_x_lo);
    cudaGetSymbolAddress((void**)&wqhi, g_wq_hi);
    cudaGetSymbolAddress((void**)&wqlo, g_wq_lo);
    cudaGetSymbolAddress((void**)&wphi, g_wp_hi);
    cudaGetSymbolAddress((void**)&wplo, g_wp_lo);
    cudaGetSymbolAddress((void**)&aohi, g_ao_hi);
    cudaGetSymbolAddress((void**)&aolo, g_ao_lo);

    cudaFuncSetAttribute(tc_gemm<0>, cudaFuncAttributeMaxDynamicSharedMemorySize, SMEM_GEMM);
    cudaFuncSetAttribute(tc_gemm<1>, cudaFuncAttributeMaxDynamicSharedMemorySize, SMEM_GEMM);

    prep_x<<<(M_TOTAL * (CH / 4)) / 256, 256>>>(x);
    prep_w<<<(QKV_N * CH / 4) / 256, 256>>>(qkv_w, wqhi, wqlo);
    prep_w<<<(CH * CH / 4) / 256, 256>>>(proj_w, wphi, wplo);

    dim3 g1(QKV_N / 128, M_TOTAL / 128);   // (6, 1568)
    tc_gemm<0><<<g1, 256, SMEM_GEMM>>>(xhi, xlo, wqhi, wqlo, qkv_b, qkv_buf);

    attn_mma_kernel<<<BATCH * NWIN * NHEAD, 32>>>(qkv_buf, table);

    dim3 g3(CH / 128, M_TOTAL / 128);      // (2, 1568)
    tc_gemm<1><<<g3, 256, SMEM_GEMM>>>(aohi, aolo, wphi, wplo, proj_b, out);
}